// round 1
// baseline (speedup 1.0000x reference)
#include <cuda_runtime.h>

#define KK 9
#define CELLS 81
#define VOL 729
#define NTHREADS 256

__global__ void sudoku_iterate_kernel(
    const float* __restrict__ s_in,
    const float* __restrict__ rm_in,
    const float* __restrict__ ri_in,
    const float* __restrict__ w_in,
    const float* __restrict__ b_in,
    float* __restrict__ s_out,
    float* __restrict__ rm_out,
    float* __restrict__ ri_out)
{
    __shared__ float sm[VOL];
    __shared__ float wsh[KK];
    __shared__ float nic_sh[CELLS];
    __shared__ int   sh_cell, sh_num;
    __shared__ float sh_mval, sh_cmc;

    const int b = blockIdx.x;
    const int t = threadIdx.x;
    const float* sb = s_in + (long)b * VOL;

    // Stage board into smem (coalesced)
    for (int i = t; i < VOL; i += NTHREADS) sm[i] = sb[i];
    if (t < KK) wsh[t] = w_in[t];
    __syncthreads();

    const float cb = b_in[0];

    // Per-cell candidate count -> nic (threads 0..80, one per cell)
    if (t < CELLS) {
        float c = cb;
        #pragma unroll
        for (int n = 0; n < KK; n++) c += sm[n * CELLS + t] * wsh[n];
        float nic = fmaxf(c - 1.0f, 0.0f);                       // relu(count-1)
        float m0  = fminf(fmaxf(1.0f - fabsf(nic), 0.0f), 1.0f) * (-(float)KK);
        nic_sh[t] = m0 - nic;
    }
    __syncthreads();

    // First-argmax over 81 cells + per-number first-argmax for chosen cell
    if (t == 0) {
        int best = 0; float bv = nic_sh[0];
        #pragma unroll
        for (int c = 1; c < CELLS; c++) {
            float v = nic_sh[c];
            if (v > bv) { bv = v; best = c; }
        }
        int bn = 0; float mv = sm[best];
        #pragma unroll
        for (int n = 1; n < KK; n++) {
            float v = sm[n * CELLS + best];
            if (v > mv) { mv = v; bn = n; }
        }
        sh_cell = best; sh_num = bn; sh_mval = mv;
        // cell_mask at chosen cell = clip(conv1x1(one_variant), 0, 1)
        sh_cmc = fminf(fmaxf(mv * wsh[bn] + cb, 0.0f), 1.0f);
    }
    __syncthreads();

    const int   cell0 = sh_cell;
    const int   num0  = sh_num;
    const float mval  = sh_mval;
    const float cmc   = sh_cmc;
    const float cme   = fminf(fmaxf(cb, 0.0f), 1.0f);  // cell_mask elsewhere (conv_b only)
    const float ri    = ri_in[b];

    const long base = (long)b * VOL;
    for (int e = t; e < VOL; e += NTHREADS) {
        int n = e / CELLS;
        int cell = e - n * CELLS;
        float s   = sm[e];
        float ov  = (cell == cell0 && n == num0) ? mval : 0.0f;  // one_variant
        float cm  = (cell == cell0) ? cmc : cme;                 // cell_mask
        float orm = s * cm * (1.0f - ov);                        // one_recursion_mask
        float rm  = rm_in[base + e];
        float rmo = fmaxf(rm, fmaxf(ri * orm, (ri - 1.0f) * ov));
        s_out[base + e]  = s * (1.0f - orm);
        rm_out[base + e] = rmo;
    }
    if (t == 0) ri_out[b] = ri + 1.0f;
}

extern "C" void kernel_launch(void* const* d_in, const int* in_sizes, int n_in,
                              void* d_out, int out_size)
{
    const float* s_in  = (const float*)d_in[0];
    const float* rm_in = (const float*)d_in[1];
    const float* ri_in = (const float*)d_in[2];
    const float* w_in  = (const float*)d_in[3];
    const float* b_in  = (const float*)d_in[4];

    const int B = in_sizes[0] / VOL;

    float* out    = (float*)d_out;
    float* s_out  = out;
    float* rm_out = out + (long)B * VOL;
    float* ri_out = out + 2L * (long)B * VOL;

    sudoku_iterate_kernel<<<B, NTHREADS>>>(s_in, rm_in, ri_in, w_in, b_in,
                                           s_out, rm_out, ri_out);
}

// round 2
// speedup vs baseline: 1.7725x; 1.7725x over previous
#include <cuda_runtime.h>

#define KK 9
#define CELLS 81
#define VOL 729
#define NT 256

__global__ void __launch_bounds__(NT) sudoku_iterate_kernel(
    const float* __restrict__ s_in,
    const float* __restrict__ rm_in,
    const float* __restrict__ ri_in,
    const float* __restrict__ w_in,
    const float* __restrict__ b_in,
    float* __restrict__ s_out,
    float* __restrict__ rm_out,
    float* __restrict__ ri_out)
{
    __shared__ int   sh_cell, sh_e0;
    __shared__ float sh_mval, sh_cmc;

    const int b = blockIdx.x;
    const int t = threadIdx.x;
    const long base = (long)b * VOL;
    const float* sb = s_in + base;
    const float* rb = rm_in + base;

    // ---- front-load all elementwise data (max MLP before any barrier) ----
    const bool has2 = (t < VOL - 2 * NT);     // t < 217
    float s0 = sb[t];
    float s1 = sb[t + NT];
    float r0 = rb[t];
    float r1 = rb[t + NT];
    float s2 = 0.0f, r2 = 0.0f;
    if (has2) { s2 = sb[t + 2 * NT]; r2 = rb[t + 2 * NT]; }
    const float ri = ri_in[b];
    const float cb = b_in[0];

    // ---- warp 0: decision (reads board straight from global, coalesced) ----
    if (t < 32) {
        float w[KK];
        #pragma unroll
        for (int n = 0; n < KK; n++) w[n] = w_in[n];

        // per-cell candidate score (nic), local first-argmax over 3 cells/lane
        float bv = -3.0e38f; int bi = 0;
        #pragma unroll
        for (int j = 0; j < 3; j++) {
            int cell = t + 32 * j;
            if (cell < CELLS) {
                float c = cb;
                #pragma unroll
                for (int n = 0; n < KK; n++)
                    c = fmaf(sb[n * CELLS + cell], w[n], c);
                float nic = fmaxf(c - 1.0f, 0.0f);                    // relu(count-1)
                float m0  = fminf(fmaxf(1.0f - fabsf(nic), 0.0f), 1.0f) * (-(float)KK);
                float v   = m0 - nic;
                if (v > bv) { bv = v; bi = cell; }                    // first max (ascending)
            }
        }
        // warp butterfly first-argmax (max value, min index on ties)
        #pragma unroll
        for (int off = 16; off; off >>= 1) {
            float ov = __shfl_xor_sync(0xffffffffu, bv, off);
            int   oi = __shfl_xor_sync(0xffffffffu, bi, off);
            if (ov > bv || (ov == bv && oi < bi)) { bv = ov; bi = oi; }
        }

        // per-number first-argmax inside the chosen cell (lanes 0..8 hold data)
        float mv = (t < KK) ? sb[t * CELLS + bi] : -3.0e38f;
        int   mi = t;
        #pragma unroll
        for (int off = 16; off; off >>= 1) {
            float ov = __shfl_xor_sync(0xffffffffu, mv, off);
            int   oi = __shfl_xor_sync(0xffffffffu, mi, off);
            if (ov > mv || (ov == mv && oi < mi)) { mv = ov; mi = oi; }
        }

        if (t == 0) {
            sh_cell = bi;
            sh_e0   = mi * CELLS + bi;
            sh_mval = mv;
            // cell_mask at chosen cell = clip(conv1x1(one_variant), 0, 1)
            sh_cmc  = fminf(fmaxf(fmaf(mv, w[mi], cb), 0.0f), 1.0f);
        }
    }
    __syncthreads();   // the ONLY barrier

    const int   cell0 = sh_cell;
    const int   e0    = sh_e0;
    const float mval  = sh_mval;
    const float cmc   = sh_cmc;
    const float cme   = fminf(fmaxf(cb, 0.0f), 1.0f);   // cell_mask away from chosen cell

    // residues mod 81 without repeated div/mod (256 mod 81 == 13)
    int q0 = t % CELLS;
    int q1 = q0 + (NT % CELLS); if (q1 >= CELLS) q1 -= CELLS;
    int q2 = q1 + (NT % CELLS); if (q2 >= CELLS) q2 -= CELLS;

    {
        float ov  = (t == e0) ? mval : 0.0f;
        float cm  = (q0 == cell0) ? cmc : cme;
        float orm = s0 * cm * (1.0f - ov);
        s_out [base + t] = s0 * (1.0f - orm);
        rm_out[base + t] = fmaxf(r0, fmaxf(ri * orm, (ri - 1.0f) * ov));
    }
    {
        int   e   = t + NT;
        float ov  = (e == e0) ? mval : 0.0f;
        float cm  = (q1 == cell0) ? cmc : cme;
        float orm = s1 * cm * (1.0f - ov);
        s_out [base + e] = s1 * (1.0f - orm);
        rm_out[base + e] = fmaxf(r1, fmaxf(ri * orm, (ri - 1.0f) * ov));
    }
    if (has2) {
        int   e   = t + 2 * NT;
        float ov  = (e == e0) ? mval : 0.0f;
        float cm  = (q2 == cell0) ? cmc : cme;
        float orm = s2 * cm * (1.0f - ov);
        s_out [base + e] = s2 * (1.0f - orm);
        rm_out[base + e] = fmaxf(r2, fmaxf(ri * orm, (ri - 1.0f) * ov));
    }
    if (t == 0) ri_out[b] = ri + 1.0f;
}

extern "C" void kernel_launch(void* const* d_in, const int* in_sizes, int n_in,
                              void* d_out, int out_size)
{
    const float* s_in  = (const float*)d_in[0];
    const float* rm_in = (const float*)d_in[1];
    const float* ri_in = (const float*)d_in[2];
    const float* w_in  = (const float*)d_in[3];
    const float* b_in  = (const float*)d_in[4];

    const int B = in_sizes[0] / VOL;

    float* out    = (float*)d_out;
    float* s_out  = out;
    float* rm_out = out + (long)B * VOL;
    float* ri_out = out + 2L * (long)B * VOL;

    sudoku_iterate_kernel<<<B, NT>>>(s_in, rm_in, ri_in, w_in, b_in,
                                     s_out, rm_out, ri_out);
}

// round 3
// speedup vs baseline: 2.1070x; 1.1887x over previous
#include <cuda_runtime.h>

#define KK    9
#define CELLS 81
#define VOL   729
#define NBRD  4
#define BVOL  (VOL * NBRD)   // 2916 floats per block (16B-aligned chunk)
#define NV4   (BVOL / 4)     // 729 float4 per block
#define NT    256

struct __align__(16) BParams {
    int   e0;      // block-relative element index of the chosen (number,cell)
    int   cell0;   // chosen cell within board (0..80)
    float mval;
    float cmc;
};

__device__ __forceinline__ void elem_op(
    float s, float r, int f, int cell,
    int e0, int cell0, float mval, float cmc, float ri, float cme,
    float& so, float& ro)
{
    float ov  = (f == e0)     ? mval : 0.0f;
    float cm  = (cell == cell0) ? cmc : cme;
    float orm = s * cm * (1.0f - ov);
    so = s * (1.0f - orm);
    ro = fmaxf(r, fmaxf(ri * orm, (ri - 1.0f) * ov));
}

__global__ void __launch_bounds__(NT) sudoku_iterate_kernel(
    const float* __restrict__ s_in,
    const float* __restrict__ rm_in,
    const float* __restrict__ ri_in,
    const float* __restrict__ w_in,
    const float* __restrict__ b_in,
    float* __restrict__ s_out,
    float* __restrict__ rm_out,
    float* __restrict__ ri_out)
{
    __shared__ BParams sh_p[NBRD];
    __shared__ float   sh_ri[NBRD];

    const int blk = blockIdx.x;
    const int t   = threadIdx.x;
    const long base = (long)blk * BVOL;

    const float4* s4p = (const float4*)(s_in + base);
    const float4* r4p = (const float4*)(rm_in + base);

    // ---- front-load everything as float4 (max bytes in flight) ----
    const bool has2 = (t < NV4 - 2 * NT);     // t < 217
    float4 s0 = s4p[t];
    float4 s1 = s4p[t + NT];
    float4 r0 = r4p[t];
    float4 r1 = r4p[t + NT];
    float4 s2 = make_float4(0,0,0,0), r2 = make_float4(0,0,0,0);
    if (has2) { s2 = s4p[t + 2 * NT]; r2 = r4p[t + 2 * NT]; }
    const float cb = b_in[0];

    // ---- warps 0..3: decision for boards 0..3 (L1-hot after front-load) ----
    const int wid = t >> 5, lane = t & 31;
    if (wid < NBRD) {
        const float* sb = s_in + base + wid * VOL;
        float w[KK];
        #pragma unroll
        for (int n = 0; n < KK; n++) w[n] = w_in[n];

        float bv = -3.0e38f; int bi = 0;
        #pragma unroll
        for (int j3 = 0; j3 < 3; j3++) {
            int cell = lane + 32 * j3;
            if (cell < CELLS) {
                float c = cb;
                #pragma unroll
                for (int n = 0; n < KK; n++)
                    c = fmaf(sb[n * CELLS + cell], w[n], c);
                float nic = fmaxf(c - 1.0f, 0.0f);
                float m0  = fminf(fmaxf(1.0f - fabsf(nic), 0.0f), 1.0f) * (-(float)KK);
                float v   = m0 - nic;
                if (v > bv) { bv = v; bi = cell; }     // first-max (ascending cells)
            }
        }
        #pragma unroll
        for (int off = 16; off; off >>= 1) {
            float ov = __shfl_xor_sync(0xffffffffu, bv, off);
            int   oi = __shfl_xor_sync(0xffffffffu, bi, off);
            if (ov > bv || (ov == bv && oi < bi)) { bv = ov; bi = oi; }
        }

        float mv = (lane < KK) ? sb[lane * CELLS + bi] : -3.0e38f;
        int   mi = lane;
        #pragma unroll
        for (int off = 16; off; off >>= 1) {
            float ov = __shfl_xor_sync(0xffffffffu, mv, off);
            int   oi = __shfl_xor_sync(0xffffffffu, mi, off);
            if (ov > mv || (ov == mv && oi < mi)) { mv = ov; mi = oi; }
        }

        if (lane == 0) {
            sh_p[wid].e0    = wid * VOL + mi * CELLS + bi;
            sh_p[wid].cell0 = bi;
            sh_p[wid].mval  = mv;
            sh_p[wid].cmc   = fminf(fmaxf(fmaf(mv, w[mi], cb), 0.0f), 1.0f);
            sh_ri[wid]      = ri_in[blk * NBRD + wid];
        }
    }
    __syncthreads();   // the ONLY barrier

    const float cme = fminf(fmaxf(cb, 0.0f), 1.0f);
    float4* so4 = (float4*)(s_out + base);
    float4* ro4 = (float4*)(rm_out + base);

    #pragma unroll
    for (int it = 0; it < 3; it++) {
        if (it == 2 && !has2) break;
        int p = t + it * NT;
        float4 sv = (it == 0) ? s0 : (it == 1) ? s1 : s2;
        float4 rv = (it == 0) ? r0 : (it == 1) ? r1 : r2;

        int e  = 4 * p;
        int j0 = (e >= VOL) + (e >= 2 * VOL) + (e >= 3 * VOL);
        int j3 = (e + 3 >= VOL) + (e + 3 >= 2 * VOL) + (e + 3 >= 3 * VOL);
        int c0 = e % CELLS;                 // 729 % 81 == 0 -> board-independent

        float4 so, ro;
        float* svp = &sv.x; float* rvp = &rv.x;
        float* sop = &so.x; float* rop = &ro.x;

        if (j0 == j3) {                     // fast path: whole float4 in one board
            BParams P = sh_p[j0];
            float  ri = sh_ri[j0];
            #pragma unroll
            for (int k = 0; k < 4; k++) {
                int cell = c0 + k; if (cell >= CELLS) cell -= CELLS;
                elem_op(svp[k], rvp[k], e + k, cell,
                        P.e0, P.cell0, P.mval, P.cmc, ri, cme, sop[k], rop[k]);
            }
        } else {                            // straddles a board boundary (rare)
            #pragma unroll
            for (int k = 0; k < 4; k++) {
                int f = e + k;
                int j = (f >= VOL) + (f >= 2 * VOL) + (f >= 3 * VOL);
                int cell = c0 + k; if (cell >= CELLS) cell -= CELLS;
                BParams P = sh_p[j];
                elem_op(svp[k], rvp[k], f, cell,
                        P.e0, P.cell0, P.mval, P.cmc, sh_ri[j], cme, sop[k], rop[k]);
            }
        }
        so4[p] = so;
        ro4[p] = ro;
    }

    if (t < NBRD) ri_out[blk * NBRD + t] = sh_ri[t] + 1.0f;
}

extern "C" void kernel_launch(void* const* d_in, const int* in_sizes, int n_in,
                              void* d_out, int out_size)
{
    const float* s_in  = (const float*)d_in[0];
    const float* rm_in = (const float*)d_in[1];
    const float* ri_in = (const float*)d_in[2];
    const float* w_in  = (const float*)d_in[3];
    const float* b_in  = (const float*)d_in[4];

    const int B = in_sizes[0] / VOL;

    float* out    = (float*)d_out;
    float* s_out  = out;
    float* rm_out = out + (long)B * VOL;
    float* ri_out = out + 2L * (long)B * VOL;

    sudoku_iterate_kernel<<<B / NBRD, NT>>>(s_in, rm_in, ri_in, w_in, b_in,
                                            s_out, rm_out, ri_out);
}